// round 13
// baseline (speedup 1.0000x reference)
#include <cuda_runtime.h>
#include <cuda_fp16.h>
#include <cstdint>
#include <math.h>

// ---------------- problem constants ----------------
#define S_TOK   1536
#define HID     2880
#define NH      64
#define NKV     8
#define DH      64
#define QKV_DIM 5120
#define QDIM    4096
#define KOFF    4096
#define VOFF    4608
#define SM_SCALE 0.125f

// ---------------- scratch ----------------
__device__ __half g_t_h[S_TOK * HID];
__device__ __half g_w1[QKV_DIM * HID];
__device__ __half g_w2[HID * QDIM];
__device__ __half g_q_h[S_TOK * QDIM];
__device__ __half g_k_h[NKV * S_TOK * DH];
__device__ __half g_vt_h[NKV * DH * S_TOK];
__device__ __half g_o_h[S_TOK * QDIM];
__device__ float g_cos[S_TOK * 32];
__device__ float g_sin[S_TOK * 32];

// ---------------- helpers ----------------
__device__ __forceinline__ uint32_t smem_u32(const void* p) {
    uint32_t a;
    asm("{ .reg .u64 t; cvta.to.shared.u64 t, %1; cvt.u32.u64 %0, t; }" : "=r"(a) : "l"(p));
    return a;
}

__device__ __forceinline__ void ldsm4(uint32_t* r, uint32_t addr) {
    asm volatile("ldmatrix.sync.aligned.m8n8.x4.shared.b16 {%0,%1,%2,%3}, [%4];"
                 : "=r"(r[0]), "=r"(r[1]), "=r"(r[2]), "=r"(r[3]) : "r"(addr));
}

__device__ __forceinline__ void mma_f16(float* c, const uint32_t* a, const uint32_t* b) {
    asm volatile("mma.sync.aligned.m16n8k16.row.col.f32.f16.f16.f32 "
                 "{%0,%1,%2,%3}, {%4,%5,%6,%7}, {%8,%9}, {%0,%1,%2,%3};"
                 : "+f"(c[0]), "+f"(c[1]), "+f"(c[2]), "+f"(c[3])
                 : "r"(a[0]), "r"(a[1]), "r"(a[2]), "r"(a[3]), "r"(b[0]), "r"(b[1]));
}

__device__ __forceinline__ uint32_t pack_h2(float a, float b) {
    __half2 h = __floats2half2_rn(a, b);
    return *(uint32_t*)&h;
}

// ============================================================
// 1) fused prelude: rmsnorm | rope tables | w1 convert | w2 convert
// ============================================================
#define NB_RMS 1536
#define NB_TAB 192                       // 1536*32 / 256
#define NB_W1  14400                     // 5120*2880/4 / 256
#define NB_W2  11520                     // 2880*4096/4 / 256
#define NB_TOTAL (NB_RMS + NB_TAB + NB_W1 + NB_W2)

__global__ void __launch_bounds__(256)
prelude_kernel(const float* __restrict__ x, const float* __restrict__ scale,
               const float4* __restrict__ w1src, const float4* __restrict__ w2src) {
    const int b = blockIdx.x;
    const int tid = threadIdx.x;
    __shared__ float red[8];

    if (b < NB_W1) {
        int i = b * 256 + tid;
        float4 v = w1src[i];
        uint2 o;
        o.x = pack_h2(v.x, v.y);
        o.y = pack_h2(v.z, v.w);
        ((uint2*)g_w1)[i] = o;
    } else if (b < NB_W1 + NB_RMS) {
        int s = b - NB_W1;
        const float4* xr = (const float4*)(x + (size_t)s * HID);
        const float4* sc = (const float4*)scale;
        float ss = 0.f;
        for (int i = tid; i < HID / 4; i += 256) {
            float4 v = xr[i];
            ss += v.x * v.x + v.y * v.y + v.z * v.z + v.w * v.w;
        }
        for (int o = 16; o > 0; o >>= 1) ss += __shfl_xor_sync(0xffffffff, ss, o);
        int wid = tid >> 5, lid = tid & 31;
        if (lid == 0) red[wid] = ss;
        __syncthreads();
        if (wid == 0) {
            float v = (lid < 8) ? red[lid] : 0.f;
            for (int o = 4; o > 0; o >>= 1) v += __shfl_xor_sync(0xffffffff, v, o);
            if (lid == 0) red[0] = v;
        }
        __syncthreads();
        float r = rsqrtf(red[0] / (float)HID + 1e-5f);
        uint2* th = (uint2*)(g_t_h + (size_t)s * HID);
        for (int i = tid; i < HID / 4; i += 256) {
            float4 v = xr[i];
            float4 g = sc[i];
            uint2 hh;
            hh.x = pack_h2(v.x * r * g.x, v.y * r * g.y);
            hh.y = pack_h2(v.z * r * g.z, v.w * r * g.w);
            th[i] = hh;
        }
    } else if (b < NB_W1 + NB_RMS + NB_TAB) {
        int gid = (b - NB_W1 - NB_RMS) * 256 + tid;
        int s = gid >> 5;
        int i = gid & 31;
        const double TWO_PI = 6.283185307179586;
        double freq = pow(150000.0, (double)(2 * i) / 64.0);
        double conc = 0.1 * log(32.0) + 1.0;
        double lo = 32.0 * log(4096.0 / (32.0 * TWO_PI)) / log(150000.0);
        double hi = 32.0 * log(4096.0 / (1.0 * TWO_PI)) / log(150000.0);
        double interp = 1.0 / (32.0 * freq);
        double extrap = 1.0 / freq;
        double ramp = ((double)i - lo) / (hi - lo);
        double mask = 1.0 - fmin(fmax(ramp, 0.0), 1.0);
        double invf = interp * (1.0 - mask) + extrap * mask;
        double f = (double)s * invf;
        g_cos[gid] = (float)(cos(f) * conc);
        g_sin[gid] = (float)(sin(f) * conc);
    } else {
        int i = (b - NB_W1 - NB_RMS - NB_TAB) * 256 + tid;
        float4 v = w2src[i];
        uint2 o;
        o.x = pack_h2(v.x, v.y);
        o.y = pack_h2(v.z, v.w);
        ((uint2*)g_w2)[i] = o;
    }
}

// ============================================================
// 2) mma.sync fp16 GEMM: CTA 128x128x64, 128 threads, 64x64 warp tile
//    MODE 0: C fp32 = A B^T + bias + resid (out proj)
//    MODE 1: qkv — fused bias + rope + scale, fp16 stores to q/k/vt
// ============================================================
#define BM 128
#define BN 128
#define BK 64
#define TILE_B 16384
#define STAGE_B (2 * TILE_B)
#define GEMM_STAGES 3
#define SMEM_TOTAL_GEMM (GEMM_STAGES * STAGE_B + 1024)

__device__ __forceinline__ void load_tile_128(uint32_t sbase, const __half* __restrict__ g,
                                              int row0, int nrows, int ldk, int k0, int tid) {
#pragma unroll
    for (int u = 0; u < 8; u++) {
        int unit = u * 128 + tid;
        int r = unit >> 3;
        int c16 = unit & 7;
        uint32_t off = (uint32_t)(r * 128 + ((c16 * 16) ^ ((r & 7) << 4)));
        int gr = row0 + r;
        int ok = (gr < nrows) ? 16 : 0;
        const __half* src = g + (size_t)((gr < nrows) ? gr : 0) * ldk + k0 + c16 * 8;
        asm volatile("cp.async.cg.shared.global [%0], [%1], 16, %2;"
                     :: "r"(sbase + off), "l"(src), "r"(ok) : "memory");
    }
}

__device__ __forceinline__ void load_stage(uint32_t st,
                                           const __half* A, const __half* B,
                                           int bm, int bn, int M, int N, int K, int k0, int tid) {
    load_tile_128(st,          A, bm, M, K, k0, tid);
    load_tile_128(st + TILE_B, B, bn, N, K, k0, tid);
}

template <int MODE>
__global__ void __launch_bounds__(128, 2)
gemm_mma(const __half* __restrict__ A, const __half* __restrict__ B,
         const float* __restrict__ bias, const float* __restrict__ resid,
         float* __restrict__ C, int M, int N, int K) {
    extern __shared__ char smem_raw[];
    uint32_t sb = (smem_u32(smem_raw) + 1023u) & ~1023u;

    const int tid = threadIdx.x;
    const int wid = tid >> 5;
    const int lane = tid & 31;
    const int wm = wid & 1;
    const int wn = wid >> 1;
    const int bm = blockIdx.y * BM;
    const int bn = blockIdx.x * BN;

    float acc[4][8][4];
#pragma unroll
    for (int i = 0; i < 4; i++)
#pragma unroll
        for (int j = 0; j < 8; j++)
#pragma unroll
            for (int k = 0; k < 4; k++) acc[i][j][k] = 0.f;

    const int a_r = wm * 64 + (lane & 15);
    const uint32_t a_cx = (uint32_t)((a_r & 7) << 4);
    const int b_r = wn * 64 + ((lane >> 4) << 3) + (lane & 7);
    const uint32_t b_cx = (uint32_t)((b_r & 7) << 4);

    const int NC = K / BK;

#pragma unroll
    for (int c = 0; c < 2; c++) {
        load_stage(sb + c * STAGE_B, A, B, bm, bn, M, N, K, c * BK, tid);
        asm volatile("cp.async.commit_group;" ::: "memory");
    }

    for (int c = 0; c < NC; c++) {
        int pf = c + 2;
        if (pf < NC) {
            load_stage(sb + (pf % GEMM_STAGES) * STAGE_B, A, B, bm, bn, M, N, K, pf * BK, tid);
        }
        asm volatile("cp.async.commit_group;" ::: "memory");
        asm volatile("cp.async.wait_group 2;" ::: "memory");
        __syncthreads();

        const uint32_t st = sb + (c % GEMM_STAGES) * STAGE_B;
#pragma unroll
        for (int ks = 0; ks < 4; ks++) {
            uint32_t ah[4][4], bh[4][4];
            const uint32_t acb = (uint32_t)(ks * 32 + ((lane >> 4) << 4));
#pragma unroll
            for (int mt = 0; mt < 4; mt++) {
                uint32_t off = (uint32_t)((a_r + mt * 16) * 128) + (acb ^ a_cx);
                ldsm4(ah[mt], st + off);
            }
            const uint32_t bcb = (uint32_t)(ks * 32 + ((lane >> 3) & 1) * 16);
#pragma unroll
            for (int p = 0; p < 4; p++) {
                uint32_t off = (uint32_t)((b_r + p * 16) * 128) + (bcb ^ b_cx);
                ldsm4(bh[p], st + TILE_B + off);
            }
#pragma unroll
            for (int mt = 0; mt < 4; mt++) {
#pragma unroll
                for (int nt = 0; nt < 8; nt++) {
                    mma_f16(acc[mt][nt], ah[mt], &bh[nt >> 1][(nt & 1) * 2]);
                }
            }
        }
        __syncthreads();
    }

    const int row0 = bm + wm * 64;
    const int col0 = bn + wn * 64;

    if (MODE == 0) {
#pragma unroll
        for (int mt = 0; mt < 4; mt++) {
#pragma unroll
            for (int nt = 0; nt < 8; nt++) {
                int r = row0 + mt * 16 + (lane >> 2);
                int c0 = col0 + nt * 8 + (lane & 3) * 2;
                if (c0 < N) {
                    float bx = bias[c0], by = bias[c0 + 1];
                    float2 v0, v1;
                    v0.x = acc[mt][nt][0] + bx; v0.y = acc[mt][nt][1] + by;
                    v1.x = acc[mt][nt][2] + bx; v1.y = acc[mt][nt][3] + by;
                    const float2 x0 = *(const float2*)(resid + (size_t)r * N + c0);
                    const float2 x1 = *(const float2*)(resid + (size_t)(r + 8) * N + c0);
                    v0.x += x0.x; v0.y += x0.y;
                    v1.x += x1.x; v1.y += x1.y;
                    *(float2*)(C + (size_t)r * N + c0) = v0;
                    *(float2*)(C + (size_t)(r + 8) * N + c0) = v1;
                }
            }
        }
    } else {
        const int head_blk = col0 >> 6;
        if (head_blk < 64) {
#pragma unroll
            for (int mt = 0; mt < 4; mt++) {
                int r = row0 + mt * 16 + (lane >> 2);
#pragma unroll
                for (int nt = 0; nt < 4; nt++) {
                    int d = nt * 8 + (lane & 3) * 2;
                    int cA = col0 + d, cB = cA + 32;
                    float b1x = bias[cA], b1y = bias[cA + 1];
                    float b2x = bias[cB], b2y = bias[cB + 1];
                    float2 c0v = *(const float2*)(g_cos + r * 32 + d);
                    float2 s0v = *(const float2*)(g_sin + r * 32 + d);
                    float2 c1v = *(const float2*)(g_cos + (r + 8) * 32 + d);
                    float2 s1v = *(const float2*)(g_sin + (r + 8) * 32 + d);
                    float x1a = acc[mt][nt][0] + b1x, x1b = acc[mt][nt][1] + b1y;
                    float x2a = acc[mt][nt + 4][0] + b2x, x2b = acc[mt][nt + 4][1] + b2y;
                    size_t o = (size_t)r * QDIM + head_blk * 64 + d;
                    *(uint32_t*)(g_q_h + o) =
                        pack_h2((x1a * c0v.x - x2a * s0v.x) * SM_SCALE,
                                (x1b * c0v.y - x2b * s0v.y) * SM_SCALE);
                    *(uint32_t*)(g_q_h + o + 32) =
                        pack_h2((x2a * c0v.x + x1a * s0v.x) * SM_SCALE,
                                (x2b * c0v.y + x1b * s0v.y) * SM_SCALE);
                    float y1a = acc[mt][nt][2] + b1x, y1b = acc[mt][nt][3] + b1y;
                    float y2a = acc[mt][nt + 4][2] + b2x, y2b = acc[mt][nt + 4][3] + b2y;
                    size_t o8 = o + (size_t)8 * QDIM;
                    *(uint32_t*)(g_q_h + o8) =
                        pack_h2((y1a * c1v.x - y2a * s1v.x) * SM_SCALE,
                                (y1b * c1v.y - y2b * s1v.y) * SM_SCALE);
                    *(uint32_t*)(g_q_h + o8 + 32) =
                        pack_h2((y2a * c1v.x + y1a * s1v.x) * SM_SCALE,
                                (y2b * c1v.y + y1b * s1v.y) * SM_SCALE);
                }
            }
        } else if (head_blk < 72) {
            const int kvh = head_blk - 64;
#pragma unroll
            for (int mt = 0; mt < 4; mt++) {
                int r = row0 + mt * 16 + (lane >> 2);
#pragma unroll
                for (int nt = 0; nt < 4; nt++) {
                    int d = nt * 8 + (lane & 3) * 2;
                    int cA = col0 + d, cB = cA + 32;
                    float b1x = bias[cA], b1y = bias[cA + 1];
                    float b2x = bias[cB], b2y = bias[cB + 1];
                    float2 c0v = *(const float2*)(g_cos + r * 32 + d);
                    float2 s0v = *(const float2*)(g_sin + r * 32 + d);
                    float2 c1v = *(const float2*)(g_cos + (r + 8) * 32 + d);
                    float2 s1v = *(const float2*)(g_sin + (r + 8) * 32 + d);
                    float x1a = acc[mt][nt][0] + b1x, x1b = acc[mt][nt][1] + b1y;
                    float x2a = acc[mt][nt + 4][0] + b2x, x2b = acc[mt][nt + 4][1] + b2y;
                    size_t o = (size_t)kvh * S_TOK * DH + (size_t)r * DH + d;
                    *(uint32_t*)(g_k_h + o) =
                        pack_h2(x1a * c0v.x - x2a * s0v.x, x1b * c0v.y - x2b * s0v.y);
                    *(uint32_t*)(g_k_h + o + 32) =
                        pack_h2(x2a * c0v.x + x1a * s0v.x, x2b * c0v.y + x1b * s0v.y);
                    float y1a = acc[mt][nt][2] + b1x, y1b = acc[mt][nt][3] + b1y;
                    float y2a = acc[mt][nt + 4][2] + b2x, y2b = acc[mt][nt + 4][3] + b2y;
                    size_t o8 = o + (size_t)8 * DH;
                    *(uint32_t*)(g_k_h + o8) =
                        pack_h2(y1a * c1v.x - y2a * s1v.x, y1b * c1v.y - y2b * s1v.y);
                    *(uint32_t*)(g_k_h + o8 + 32) =
                        pack_h2(y2a * c1v.x + y1a * s1v.x, y2b * c1v.y + y1b * s1v.y);
                }
            }
        } else {
            const int kvh = head_blk - 72;
            __half* vt = g_vt_h + (size_t)kvh * DH * S_TOK;
#pragma unroll
            for (int mt = 0; mt < 4; mt++) {
                int r = row0 + mt * 16 + (lane >> 2);
#pragma unroll
                for (int nt = 0; nt < 8; nt++) {
                    int d = nt * 8 + (lane & 3) * 2;
                    float bx = bias[col0 + d], by = bias[col0 + d + 1];
                    vt[(size_t)d * S_TOK + r]           = __float2half_rn(acc[mt][nt][0] + bx);
                    vt[(size_t)(d + 1) * S_TOK + r]     = __float2half_rn(acc[mt][nt][1] + by);
                    vt[(size_t)d * S_TOK + r + 8]       = __float2half_rn(acc[mt][nt][2] + bx);
                    vt[(size_t)(d + 1) * S_TOK + r + 8] = __float2half_rn(acc[mt][nt][3] + by);
                }
            }
        }
    }
}

// ============================================================
// 3) tensorized flash attention with sinks
//    block: 128 q rows x 1 head, 4 warps; 3-buffer KV pipeline
// ============================================================
#define ATT_STAGE 16384
#define ATT_SMEM_TOTAL (1024 + 16384 + 3 * ATT_STAGE)

__device__ __forceinline__ void stage128q(uint32_t sbase, const __half* __restrict__ g,
                                          int row_stride, int tid) {
#pragma unroll
    for (int u = 0; u < 8; u++) {
        int unit = u * 128 + tid;
        int r = unit >> 3, c16 = unit & 7;
        uint32_t off = (uint32_t)(r * 128 + ((c16 * 16) ^ ((r & 7) << 4)));
        const __half* src = g + (size_t)r * row_stride + c16 * 8;
        asm volatile("cp.async.cg.shared.global [%0], [%1], 16;"
                     :: "r"(sbase + off), "l"(src) : "memory");
    }
}

__device__ __forceinline__ void stage64(uint32_t sbase, const __half* __restrict__ g,
                                        int row_stride, int tid) {
#pragma unroll
    for (int u = 0; u < 4; u++) {
        int unit = u * 128 + tid;
        int r = unit >> 3, c16 = unit & 7;
        uint32_t off = (uint32_t)(r * 128 + ((c16 * 16) ^ ((r & 7) << 4)));
        const __half* src = g + (size_t)r * row_stride + c16 * 8;
        asm volatile("cp.async.cg.shared.global [%0], [%1], 16;"
                     :: "r"(sbase + off), "l"(src) : "memory");
    }
}

__device__ __forceinline__ void stage_kv(uint32_t base, int kt, int kv, int tid) {
    const __half* kh = g_k_h + (size_t)kv * S_TOK * DH + (size_t)kt * 64 * DH;
    const __half* vh = g_vt_h + (size_t)kv * DH * S_TOK + kt * 64;
    stage64(base,        kh, DH, tid);
    stage64(base + 8192, vh, S_TOK, tid);
}

__global__ void __launch_bounds__(128)
attn_mma_kernel(const float* __restrict__ sinks) {
    extern __shared__ char sraw[];
    uint32_t sb = (smem_u32(sraw) + 1023u) & ~1023u;
    const uint32_t QB = sb, KVB = sb + 16384;

    const int qt = (int)gridDim.x - 1 - (int)blockIdx.x;
    const int h = blockIdx.y, kv = h & 7;
    const int tid = threadIdx.x, w = tid >> 5, lane = tid & 31;

    const int KT = 2 * qt + 2;

    // prologue: Q + KV tile 0 (group), then KV tile 1 (group)
    stage128q(QB, g_q_h + (size_t)(qt * 128) * QDIM + h * 64, QDIM, tid);
    stage_kv(KVB, 0, kv, tid);
    asm volatile("cp.async.commit_group;" ::: "memory");
    stage_kv(KVB + ATT_STAGE, 1, kv, tid);
    asm volatile("cp.async.commit_group;" ::: "memory");
    asm volatile("cp.async.wait_group 1;" ::: "memory");
    __syncthreads();

    uint32_t qh[2][4][4];
#pragma unroll
    for (int mt = 0; mt < 2; mt++) {
        int a_r = w * 32 + mt * 16 + (lane & 15);
        uint32_t ax = (uint32_t)((a_r & 7) << 4);
#pragma unroll
        for (int kt4 = 0; kt4 < 4; kt4++) {
            uint32_t cb = (uint32_t)(kt4 * 32 + ((lane >> 4) << 4));
            uint32_t off = (uint32_t)(a_r * 128) + (cb ^ ax);
            ldsm4(qh[mt][kt4], QB + off);
        }
    }

    float O[2][8][4];
#pragma unroll
    for (int mt = 0; mt < 2; mt++)
#pragma unroll
        for (int nt = 0; nt < 8; nt++)
#pragma unroll
            for (int j = 0; j < 4; j++) O[mt][nt][j] = 0.f;

    float snk = sinks[h];
    float mxA[2] = {snk, snk}, mxB[2] = {snk, snk};
    float lA[2] = {1.f, 1.f}, lB[2] = {1.f, 1.f};

    const int rbase = qt * 128 + w * 32 + (lane >> 2);
    const int b_rbase = ((lane >> 4) << 3) + (lane & 7);
    const uint32_t bsel = (uint32_t)(((lane >> 3) & 1) * 16);

    // 3-buffer pipeline: iter kt prefetches kt+2 into (kt+2)%3
    for (int kt = 0; kt < KT; kt++) {
        if (kt + 2 < KT)
            stage_kv(KVB + ((kt + 2) % 3) * ATT_STAGE, kt + 2, kv, tid);
        asm volatile("cp.async.commit_group;" ::: "memory");
        asm volatile("cp.async.wait_group 2;" ::: "memory");
        __syncthreads();

        const uint32_t kb = KVB + (kt % 3) * ATT_STAGE;
        const uint32_t vb = kb + 8192;

        float sc[2][8][4];
#pragma unroll
        for (int mt = 0; mt < 2; mt++)
#pragma unroll
            for (int nt = 0; nt < 8; nt++)
#pragma unroll
                for (int j = 0; j < 4; j++) sc[mt][nt][j] = 0.f;

#pragma unroll
        for (int kt4 = 0; kt4 < 4; kt4++) {
#pragma unroll
            for (int kg = 0; kg < 4; kg++) {
                int b_r = kg * 16 + b_rbase;
                uint32_t off = (uint32_t)(b_r * 128) + (((uint32_t)(kt4 * 32) + bsel) ^ ((uint32_t)((b_r & 7) << 4)));
                uint32_t bh4[4];
                ldsm4(bh4, kb + off);
#pragma unroll
                for (int mt = 0; mt < 2; mt++) {
#pragma unroll
                    for (int n2 = 0; n2 < 2; n2++) {
                        mma_f16(sc[mt][2 * kg + n2], qh[mt][kt4], &bh4[n2 * 2]);
                    }
                }
            }
        }

        if (kt >= 2 * qt) {
#pragma unroll
            for (int mt = 0; mt < 2; mt++) {
                int row = rbase + mt * 16;
#pragma unroll
                for (int nt = 0; nt < 8; nt++) {
                    int key = kt * 64 + nt * 8 + 2 * (lane & 3);
                    if (key > row)         sc[mt][nt][0] = -1e30f;
                    if (key + 1 > row)     sc[mt][nt][1] = -1e30f;
                    if (key > row + 8)     sc[mt][nt][2] = -1e30f;
                    if (key + 1 > row + 8) sc[mt][nt][3] = -1e30f;
                }
            }
        }

#pragma unroll
        for (int mt = 0; mt < 2; mt++) {
            float r0 = -1e30f, r1 = -1e30f;
#pragma unroll
            for (int nt = 0; nt < 8; nt++) {
                r0 = fmaxf(r0, fmaxf(sc[mt][nt][0], sc[mt][nt][1]));
                r1 = fmaxf(r1, fmaxf(sc[mt][nt][2], sc[mt][nt][3]));
            }
            r0 = fmaxf(r0, __shfl_xor_sync(0xffffffffu, r0, 1));
            r0 = fmaxf(r0, __shfl_xor_sync(0xffffffffu, r0, 2));
            r1 = fmaxf(r1, __shfl_xor_sync(0xffffffffu, r1, 1));
            r1 = fmaxf(r1, __shfl_xor_sync(0xffffffffu, r1, 2));
            float mA2 = fmaxf(mxA[mt], r0), mB2 = fmaxf(mxB[mt], r1);
            float cA = __expf(mxA[mt] - mA2), cB = __expf(mxB[mt] - mB2);
            mxA[mt] = mA2; mxB[mt] = mB2;

            float sA = 0.f, sB = 0.f;
#pragma unroll
            for (int nt = 0; nt < 8; nt++) {
                sc[mt][nt][0] = __expf(sc[mt][nt][0] - mA2);
                sc[mt][nt][1] = __expf(sc[mt][nt][1] - mA2);
                sc[mt][nt][2] = __expf(sc[mt][nt][2] - mB2);
                sc[mt][nt][3] = __expf(sc[mt][nt][3] - mB2);
                sA += sc[mt][nt][0] + sc[mt][nt][1];
                sB += sc[mt][nt][2] + sc[mt][nt][3];
            }
            sA += __shfl_xor_sync(0xffffffffu, sA, 1);
            sA += __shfl_xor_sync(0xffffffffu, sA, 2);
            sB += __shfl_xor_sync(0xffffffffu, sB, 1);
            sB += __shfl_xor_sync(0xffffffffu, sB, 2);
            lA[mt] = lA[mt] * cA + sA;
            lB[mt] = lB[mt] * cB + sB;
#pragma unroll
            for (int nt = 0; nt < 8; nt++) {
                O[mt][nt][0] *= cA; O[mt][nt][1] *= cA;
                O[mt][nt][2] *= cB; O[mt][nt][3] *= cB;
            }
        }

#pragma unroll
        for (int sg = 0; sg < 4; sg++) {
            uint32_t ph[2][4];
#pragma unroll
            for (int mt = 0; mt < 2; mt++) {
                ph[mt][0] = pack_h2(sc[mt][2 * sg][0], sc[mt][2 * sg][1]);
                ph[mt][1] = pack_h2(sc[mt][2 * sg][2], sc[mt][2 * sg][3]);
                ph[mt][2] = pack_h2(sc[mt][2 * sg + 1][0], sc[mt][2 * sg + 1][1]);
                ph[mt][3] = pack_h2(sc[mt][2 * sg + 1][2], sc[mt][2 * sg + 1][3]);
            }
#pragma unroll
            for (int dg = 0; dg < 4; dg++) {
                int b_r = dg * 16 + b_rbase;
                uint32_t off = (uint32_t)(b_r * 128) + (((uint32_t)(sg * 32) + bsel) ^ ((uint32_t)((b_r & 7) << 4)));
                uint32_t vh4[4];
                ldsm4(vh4, vb + off);
#pragma unroll
                for (int mt = 0; mt < 2; mt++) {
#pragma unroll
                    for (int n2 = 0; n2 < 2; n2++) {
                        mma_f16(O[mt][2 * dg + n2], ph[mt], &vh4[n2 * 2]);
                    }
                }
            }
        }
        __syncthreads();
    }

#pragma unroll
    for (int mt = 0; mt < 2; mt++) {
        float iA = 1.f / lA[mt], iB = 1.f / lB[mt];
        int row = rbase + mt * 16;
        size_t r0o = (size_t)row * QDIM + h * 64;
        size_t r1o = r0o + (size_t)8 * QDIM;
#pragma unroll
        for (int nt = 0; nt < 8; nt++) {
            int c = nt * 8 + 2 * (lane & 3);
            *(uint32_t*)(g_o_h + r0o + c) = pack_h2(O[mt][nt][0] * iA, O[mt][nt][1] * iA);
            *(uint32_t*)(g_o_h + r1o + c) = pack_h2(O[mt][nt][2] * iB, O[mt][nt][3] * iB);
        }
    }
}

// ============================================================
// launch
// ============================================================
extern "C" void kernel_launch(void* const* d_in, const int* in_sizes, int n_in,
                              void* d_out, int out_size) {
    const float* x          = (const float*)d_in[0];
    const float* sinks      = (const float*)d_in[1];
    const float* norm_scale = (const float*)d_in[2];
    const float* qkv_w      = (const float*)d_in[3];
    const float* qkv_b      = (const float*)d_in[4];
    const float* out_w      = (const float*)d_in[5];
    const float* out_b      = (const float*)d_in[6];
    float* out = (float*)d_out;

    __half *th, *w1, *w2, *oh;
    cudaGetSymbolAddress((void**)&th, g_t_h);
    cudaGetSymbolAddress((void**)&w1, g_w1);
    cudaGetSymbolAddress((void**)&w2, g_w2);
    cudaGetSymbolAddress((void**)&oh, g_o_h);

    cudaFuncSetAttribute(gemm_mma<0>, cudaFuncAttributeMaxDynamicSharedMemorySize, SMEM_TOTAL_GEMM);
    cudaFuncSetAttribute(gemm_mma<1>, cudaFuncAttributeMaxDynamicSharedMemorySize, SMEM_TOTAL_GEMM);
    cudaFuncSetAttribute(attn_mma_kernel, cudaFuncAttributeMaxDynamicSharedMemorySize, ATT_SMEM_TOTAL);

    // fused prelude: w1 convert | rmsnorm | rope tables | w2 convert
    prelude_kernel<<<NB_TOTAL, 256>>>(x, norm_scale,
                                      (const float4*)qkv_w, (const float4*)out_w);

    // qkv GEMM with fused bias+rope+scale epilogue -> g_q_h / g_k_h / g_vt_h
    gemm_mma<1><<<dim3(QKV_DIM / BN, S_TOK / BM), 128, SMEM_TOTAL_GEMM>>>(
        th, w1, qkv_b, nullptr, nullptr, S_TOK, QKV_DIM, HID);

    // tensorized attention (128-row q tiles, 3-buffer KV pipeline)
    attn_mma_kernel<<<dim3(S_TOK / 128, NH), 128, ATT_SMEM_TOTAL>>>(sinks);

    // y = o @ out_w^T + out_b + x
    gemm_mma<0><<<dim3((HID + BN - 1) / BN, S_TOK / BM), 128, SMEM_TOTAL_GEMM>>>(
        oh, w2, out_b, x, out, S_TOK, HID, QDIM);
}

// round 14
// speedup vs baseline: 1.1881x; 1.1881x over previous
#include <cuda_runtime.h>
#include <cuda_fp16.h>
#include <cstdint>
#include <math.h>

// ---------------- problem constants ----------------
#define S_TOK   1536
#define HID     2880
#define NH      64
#define NKV     8
#define DH      64
#define QKV_DIM 5120
#define QDIM    4096
#define KOFF    4096
#define VOFF    4608
#define SM_SCALE 0.125f

// ---------------- scratch ----------------
__device__ __half g_t_h[S_TOK * HID];
__device__ __half g_w1[QKV_DIM * HID];
__device__ __half g_w2[HID * QDIM];
__device__ __half g_q_h[S_TOK * QDIM];
__device__ __half g_k_h[NKV * S_TOK * DH];
__device__ __half g_vt_h[NKV * DH * S_TOK];
__device__ __half g_o_h[S_TOK * QDIM];
__device__ float g_cos[S_TOK * 32];
__device__ float g_sin[S_TOK * 32];

// ---------------- helpers ----------------
__device__ __forceinline__ uint32_t smem_u32(const void* p) {
    uint32_t a;
    asm("{ .reg .u64 t; cvta.to.shared.u64 t, %1; cvt.u32.u64 %0, t; }" : "=r"(a) : "l"(p));
    return a;
}

__device__ __forceinline__ void ldsm4(uint32_t* r, uint32_t addr) {
    asm volatile("ldmatrix.sync.aligned.m8n8.x4.shared.b16 {%0,%1,%2,%3}, [%4];"
                 : "=r"(r[0]), "=r"(r[1]), "=r"(r[2]), "=r"(r[3]) : "r"(addr));
}

__device__ __forceinline__ void mma_f16(float* c, const uint32_t* a, const uint32_t* b) {
    asm volatile("mma.sync.aligned.m16n8k16.row.col.f32.f16.f16.f32 "
                 "{%0,%1,%2,%3}, {%4,%5,%6,%7}, {%8,%9}, {%0,%1,%2,%3};"
                 : "+f"(c[0]), "+f"(c[1]), "+f"(c[2]), "+f"(c[3])
                 : "r"(a[0]), "r"(a[1]), "r"(a[2]), "r"(a[3]), "r"(b[0]), "r"(b[1]));
}

__device__ __forceinline__ uint32_t pack_h2(float a, float b) {
    __half2 h = __floats2half2_rn(a, b);
    return *(uint32_t*)&h;
}

// ============================================================
// 1) RMSNorm -> fp16
// ============================================================
__global__ void rmsnorm_kernel(const float* __restrict__ x,
                               const float* __restrict__ scale) {
    int s = blockIdx.x;
    const float4* xr = (const float4*)(x + (size_t)s * HID);
    const float4* sc = (const float4*)scale;

    float ss = 0.f;
    for (int i = threadIdx.x; i < HID / 4; i += blockDim.x) {
        float4 v = xr[i];
        ss += v.x * v.x + v.y * v.y + v.z * v.z + v.w * v.w;
    }
    for (int o = 16; o > 0; o >>= 1) ss += __shfl_xor_sync(0xffffffff, ss, o);
    __shared__ float red[8];
    int wid = threadIdx.x >> 5, lid = threadIdx.x & 31;
    if (lid == 0) red[wid] = ss;
    __syncthreads();
    if (wid == 0) {
        float v = (lid < (blockDim.x >> 5)) ? red[lid] : 0.f;
        for (int o = 4; o > 0; o >>= 1) v += __shfl_xor_sync(0xffffffff, v, o);
        if (lid == 0) red[0] = v;
    }
    __syncthreads();
    float r = rsqrtf(red[0] / (float)HID + 1e-5f);

    uint2* th = (uint2*)(g_t_h + (size_t)s * HID);
    for (int i = threadIdx.x; i < HID / 4; i += blockDim.x) {
        float4 v = xr[i];
        float4 g = sc[i];
        uint2 hh;
        hh.x = pack_h2(v.x * r * g.x, v.y * r * g.y);
        hh.y = pack_h2(v.z * r * g.z, v.w * r * g.w);
        th[i] = hh;
    }
}

// ============================================================
// 2) fp32 -> fp16 convert: both weights in ONE launch
//    (pure elementwise, no smem/sync — two contiguous block ranges)
// ============================================================
#define NB_W1 14400                 // 5120*2880/4 / 256
#define NB_W2 11520                 // 2880*4096/4 / 256

__global__ void __launch_bounds__(256)
convert_both_kernel(const float4* __restrict__ w1src, const float4* __restrict__ w2src) {
    int b = blockIdx.x;
    if (b < NB_W1) {
        int i = b * 256 + threadIdx.x;
        float4 v = w1src[i];
        uint2 o;
        o.x = pack_h2(v.x, v.y);
        o.y = pack_h2(v.z, v.w);
        ((uint2*)g_w1)[i] = o;
    } else {
        int i = (b - NB_W1) * 256 + threadIdx.x;
        float4 v = w2src[i];
        uint2 o;
        o.x = pack_h2(v.x, v.y);
        o.y = pack_h2(v.z, v.w);
        ((uint2*)g_w2)[i] = o;
    }
}

// ============================================================
// 3) YaRN RoPE tables (fp64, matches reference) — runs FIRST
// ============================================================
__global__ void rope_tables_kernel() {
    int gid = blockIdx.x * blockDim.x + threadIdx.x;
    if (gid >= S_TOK * 32) return;
    int s = gid >> 5;
    int i = gid & 31;
    const double TWO_PI = 6.283185307179586;
    double freq = pow(150000.0, (double)(2 * i) / 64.0);
    double conc = 0.1 * log(32.0) + 1.0;
    double lo = 32.0 * log(4096.0 / (32.0 * TWO_PI)) / log(150000.0);
    double hi = 32.0 * log(4096.0 / (1.0 * TWO_PI)) / log(150000.0);
    double interp = 1.0 / (32.0 * freq);
    double extrap = 1.0 / freq;
    double ramp = ((double)i - lo) / (hi - lo);
    double mask = 1.0 - fmin(fmax(ramp, 0.0), 1.0);
    double invf = interp * (1.0 - mask) + extrap * mask;
    double f = (double)s * invf;
    g_cos[gid] = (float)(cos(f) * conc);
    g_sin[gid] = (float)(sin(f) * conc);
}

// ============================================================
// 4) mma.sync fp16 GEMM: CTA 128x128x64, 128 threads, 64x64 warp tile
//    MODE 0: C fp32 = A B^T + bias + resid (out proj)
//    MODE 1: qkv — fused bias + rope + scale, fp16 stores to q/k/vt
// ============================================================
#define BM 128
#define BN 128
#define BK 64
#define TILE_B 16384
#define STAGE_B (2 * TILE_B)
#define GEMM_STAGES 3
#define SMEM_TOTAL_GEMM (GEMM_STAGES * STAGE_B + 1024)

__device__ __forceinline__ void load_tile_128(uint32_t sbase, const __half* __restrict__ g,
                                              int row0, int nrows, int ldk, int k0, int tid) {
#pragma unroll
    for (int u = 0; u < 8; u++) {
        int unit = u * 128 + tid;
        int r = unit >> 3;
        int c16 = unit & 7;
        uint32_t off = (uint32_t)(r * 128 + ((c16 * 16) ^ ((r & 7) << 4)));
        int gr = row0 + r;
        int ok = (gr < nrows) ? 16 : 0;
        const __half* src = g + (size_t)((gr < nrows) ? gr : 0) * ldk + k0 + c16 * 8;
        asm volatile("cp.async.cg.shared.global [%0], [%1], 16, %2;"
                     :: "r"(sbase + off), "l"(src), "r"(ok) : "memory");
    }
}

__device__ __forceinline__ void load_stage(uint32_t st,
                                           const __half* A, const __half* B,
                                           int bm, int bn, int M, int N, int K, int k0, int tid) {
    load_tile_128(st,          A, bm, M, K, k0, tid);
    load_tile_128(st + TILE_B, B, bn, N, K, k0, tid);
}

template <int MODE>
__global__ void __launch_bounds__(128, 2)
gemm_mma(const __half* __restrict__ A, const __half* __restrict__ B,
         const float* __restrict__ bias, const float* __restrict__ resid,
         float* __restrict__ C, int M, int N, int K) {
    extern __shared__ char smem_raw[];
    uint32_t sb = (smem_u32(smem_raw) + 1023u) & ~1023u;

    const int tid = threadIdx.x;
    const int wid = tid >> 5;
    const int lane = tid & 31;
    const int wm = wid & 1;
    const int wn = wid >> 1;
    const int bm = blockIdx.y * BM;
    const int bn = blockIdx.x * BN;

    float acc[4][8][4];
#pragma unroll
    for (int i = 0; i < 4; i++)
#pragma unroll
        for (int j = 0; j < 8; j++)
#pragma unroll
            for (int k = 0; k < 4; k++) acc[i][j][k] = 0.f;

    const int a_r = wm * 64 + (lane & 15);
    const uint32_t a_cx = (uint32_t)((a_r & 7) << 4);
    const int b_r = wn * 64 + ((lane >> 4) << 3) + (lane & 7);
    const uint32_t b_cx = (uint32_t)((b_r & 7) << 4);

    const int NC = K / BK;

#pragma unroll
    for (int c = 0; c < 2; c++) {
        load_stage(sb + c * STAGE_B, A, B, bm, bn, M, N, K, c * BK, tid);
        asm volatile("cp.async.commit_group;" ::: "memory");
    }

    for (int c = 0; c < NC; c++) {
        int pf = c + 2;
        if (pf < NC) {
            load_stage(sb + (pf % GEMM_STAGES) * STAGE_B, A, B, bm, bn, M, N, K, pf * BK, tid);
        }
        asm volatile("cp.async.commit_group;" ::: "memory");
        asm volatile("cp.async.wait_group 2;" ::: "memory");
        __syncthreads();

        const uint32_t st = sb + (c % GEMM_STAGES) * STAGE_B;
#pragma unroll
        for (int ks = 0; ks < 4; ks++) {
            uint32_t ah[4][4], bh[4][4];
            const uint32_t acb = (uint32_t)(ks * 32 + ((lane >> 4) << 4));
#pragma unroll
            for (int mt = 0; mt < 4; mt++) {
                uint32_t off = (uint32_t)((a_r + mt * 16) * 128) + (acb ^ a_cx);
                ldsm4(ah[mt], st + off);
            }
            const uint32_t bcb = (uint32_t)(ks * 32 + ((lane >> 3) & 1) * 16);
#pragma unroll
            for (int p = 0; p < 4; p++) {
                uint32_t off = (uint32_t)((b_r + p * 16) * 128) + (bcb ^ b_cx);
                ldsm4(bh[p], st + TILE_B + off);
            }
#pragma unroll
            for (int mt = 0; mt < 4; mt++) {
#pragma unroll
                for (int nt = 0; nt < 8; nt++) {
                    mma_f16(acc[mt][nt], ah[mt], &bh[nt >> 1][(nt & 1) * 2]);
                }
            }
        }
        __syncthreads();
    }

    const int row0 = bm + wm * 64;
    const int col0 = bn + wn * 64;

    if (MODE == 0) {
#pragma unroll
        for (int mt = 0; mt < 4; mt++) {
#pragma unroll
            for (int nt = 0; nt < 8; nt++) {
                int r = row0 + mt * 16 + (lane >> 2);
                int c0 = col0 + nt * 8 + (lane & 3) * 2;
                if (c0 < N) {
                    float bx = bias[c0], by = bias[c0 + 1];
                    float2 v0, v1;
                    v0.x = acc[mt][nt][0] + bx; v0.y = acc[mt][nt][1] + by;
                    v1.x = acc[mt][nt][2] + bx; v1.y = acc[mt][nt][3] + by;
                    const float2 x0 = *(const float2*)(resid + (size_t)r * N + c0);
                    const float2 x1 = *(const float2*)(resid + (size_t)(r + 8) * N + c0);
                    v0.x += x0.x; v0.y += x0.y;
                    v1.x += x1.x; v1.y += x1.y;
                    *(float2*)(C + (size_t)r * N + c0) = v0;
                    *(float2*)(C + (size_t)(r + 8) * N + c0) = v1;
                }
            }
        }
    } else {
        const int head_blk = col0 >> 6;
        if (head_blk < 64) {
#pragma unroll
            for (int mt = 0; mt < 4; mt++) {
                int r = row0 + mt * 16 + (lane >> 2);
#pragma unroll
                for (int nt = 0; nt < 4; nt++) {
                    int d = nt * 8 + (lane & 3) * 2;
                    int cA = col0 + d, cB = cA + 32;
                    float b1x = bias[cA], b1y = bias[cA + 1];
                    float b2x = bias[cB], b2y = bias[cB + 1];
                    float2 c0v = *(const float2*)(g_cos + r * 32 + d);
                    float2 s0v = *(const float2*)(g_sin + r * 32 + d);
                    float2 c1v = *(const float2*)(g_cos + (r + 8) * 32 + d);
                    float2 s1v = *(const float2*)(g_sin + (r + 8) * 32 + d);
                    float x1a = acc[mt][nt][0] + b1x, x1b = acc[mt][nt][1] + b1y;
                    float x2a = acc[mt][nt + 4][0] + b2x, x2b = acc[mt][nt + 4][1] + b2y;
                    size_t o = (size_t)r * QDIM + head_blk * 64 + d;
                    *(uint32_t*)(g_q_h + o) =
                        pack_h2((x1a * c0v.x - x2a * s0v.x) * SM_SCALE,
                                (x1b * c0v.y - x2b * s0v.y) * SM_SCALE);
                    *(uint32_t*)(g_q_h + o + 32) =
                        pack_h2((x2a * c0v.x + x1a * s0v.x) * SM_SCALE,
                                (x2b * c0v.y + x1b * s0v.y) * SM_SCALE);
                    float y1a = acc[mt][nt][2] + b1x, y1b = acc[mt][nt][3] + b1y;
                    float y2a = acc[mt][nt + 4][2] + b2x, y2b = acc[mt][nt + 4][3] + b2y;
                    size_t o8 = o + (size_t)8 * QDIM;
                    *(uint32_t*)(g_q_h + o8) =
                        pack_h2((y1a * c1v.x - y2a * s1v.x) * SM_SCALE,
                                (y1b * c1v.y - y2b * s1v.y) * SM_SCALE);
                    *(uint32_t*)(g_q_h + o8 + 32) =
                        pack_h2((y2a * c1v.x + y1a * s1v.x) * SM_SCALE,
                                (y2b * c1v.y + y1b * s1v.y) * SM_SCALE);
                }
            }
        } else if (head_blk < 72) {
            const int kvh = head_blk - 64;
#pragma unroll
            for (int mt = 0; mt < 4; mt++) {
                int r = row0 + mt * 16 + (lane >> 2);
#pragma unroll
                for (int nt = 0; nt < 4; nt++) {
                    int d = nt * 8 + (lane & 3) * 2;
                    int cA = col0 + d, cB = cA + 32;
                    float b1x = bias[cA], b1y = bias[cA + 1];
                    float b2x = bias[cB], b2y = bias[cB + 1];
                    float2 c0v = *(const float2*)(g_cos + r * 32 + d);
                    float2 s0v = *(const float2*)(g_sin + r * 32 + d);
                    float2 c1v = *(const float2*)(g_cos + (r + 8) * 32 + d);
                    float2 s1v = *(const float2*)(g_sin + (r + 8) * 32 + d);
                    float x1a = acc[mt][nt][0] + b1x, x1b = acc[mt][nt][1] + b1y;
                    float x2a = acc[mt][nt + 4][0] + b2x, x2b = acc[mt][nt + 4][1] + b2y;
                    size_t o = (size_t)kvh * S_TOK * DH + (size_t)r * DH + d;
                    *(uint32_t*)(g_k_h + o) =
                        pack_h2(x1a * c0v.x - x2a * s0v.x, x1b * c0v.y - x2b * s0v.y);
                    *(uint32_t*)(g_k_h + o + 32) =
                        pack_h2(x2a * c0v.x + x1a * s0v.x, x2b * c0v.y + x1b * s0v.y);
                    float y1a = acc[mt][nt][2] + b1x, y1b = acc[mt][nt][3] + b1y;
                    float y2a = acc[mt][nt + 4][2] + b2x, y2b = acc[mt][nt + 4][3] + b2y;
                    size_t o8 = o + (size_t)8 * DH;
                    *(uint32_t*)(g_k_h + o8) =
                        pack_h2(y1a * c1v.x - y2a * s1v.x, y1b * c1v.y - y2b * s1v.y);
                    *(uint32_t*)(g_k_h + o8 + 32) =
                        pack_h2(y2a * c1v.x + y1a * s1v.x, y2b * c1v.y + y1b * s1v.y);
                }
            }
        } else {
            const int kvh = head_blk - 72;
            __half* vt = g_vt_h + (size_t)kvh * DH * S_TOK;
#pragma unroll
            for (int mt = 0; mt < 4; mt++) {
                int r = row0 + mt * 16 + (lane >> 2);
#pragma unroll
                for (int nt = 0; nt < 8; nt++) {
                    int d = nt * 8 + (lane & 3) * 2;
                    float bx = bias[col0 + d], by = bias[col0 + d + 1];
                    vt[(size_t)d * S_TOK + r]           = __float2half_rn(acc[mt][nt][0] + bx);
                    vt[(size_t)(d + 1) * S_TOK + r]     = __float2half_rn(acc[mt][nt][1] + by);
                    vt[(size_t)d * S_TOK + r + 8]       = __float2half_rn(acc[mt][nt][2] + bx);
                    vt[(size_t)(d + 1) * S_TOK + r + 8] = __float2half_rn(acc[mt][nt][3] + by);
                }
            }
        }
    }
}

// ============================================================
// 5) tensorized flash attention with sinks
//    block: 128 q rows x 1 head, 4 warps (32 rows each, mt=2)
//    double-buffered KV; fully-masked warp-tiles skipped
// ============================================================
#define ATT_STAGE 16384
#define ATT_SMEM_TOTAL (1024 + 16384 + 2 * ATT_STAGE)

__device__ __forceinline__ void stage128q(uint32_t sbase, const __half* __restrict__ g,
                                          int row_stride, int tid) {
#pragma unroll
    for (int u = 0; u < 8; u++) {
        int unit = u * 128 + tid;
        int r = unit >> 3, c16 = unit & 7;
        uint32_t off = (uint32_t)(r * 128 + ((c16 * 16) ^ ((r & 7) << 4)));
        const __half* src = g + (size_t)r * row_stride + c16 * 8;
        asm volatile("cp.async.cg.shared.global [%0], [%1], 16;"
                     :: "r"(sbase + off), "l"(src) : "memory");
    }
}

__device__ __forceinline__ void stage64(uint32_t sbase, const __half* __restrict__ g,
                                        int row_stride, int tid) {
#pragma unroll
    for (int u = 0; u < 4; u++) {
        int unit = u * 128 + tid;
        int r = unit >> 3, c16 = unit & 7;
        uint32_t off = (uint32_t)(r * 128 + ((c16 * 16) ^ ((r & 7) << 4)));
        const __half* src = g + (size_t)r * row_stride + c16 * 8;
        asm volatile("cp.async.cg.shared.global [%0], [%1], 16;"
                     :: "r"(sbase + off), "l"(src) : "memory");
    }
}

__device__ __forceinline__ void stage_kv(uint32_t base, int kt, int kv, int tid) {
    const __half* kh = g_k_h + (size_t)kv * S_TOK * DH + (size_t)kt * 64 * DH;
    const __half* vh = g_vt_h + (size_t)kv * DH * S_TOK + kt * 64;
    stage64(base,        kh, DH, tid);
    stage64(base + 8192, vh, S_TOK, tid);
}

__global__ void __launch_bounds__(128)
attn_mma_kernel(const float* __restrict__ sinks) {
    extern __shared__ char sraw[];
    uint32_t sb = (smem_u32(sraw) + 1023u) & ~1023u;
    const uint32_t QB = sb, KVB = sb + 16384;

    const int qt = (int)gridDim.x - 1 - (int)blockIdx.x;
    const int h = blockIdx.y, kv = h & 7;
    const int tid = threadIdx.x, w = tid >> 5, lane = tid & 31;

    stage128q(QB, g_q_h + (size_t)(qt * 128) * QDIM + h * 64, QDIM, tid);
    stage_kv(KVB, 0, kv, tid);
    asm volatile("cp.async.commit_group;" ::: "memory");
    asm volatile("cp.async.wait_group 0;" ::: "memory");
    __syncthreads();

    uint32_t qh[2][4][4];
#pragma unroll
    for (int mt = 0; mt < 2; mt++) {
        int a_r = w * 32 + mt * 16 + (lane & 15);
        uint32_t ax = (uint32_t)((a_r & 7) << 4);
#pragma unroll
        for (int kt4 = 0; kt4 < 4; kt4++) {
            uint32_t cb = (uint32_t)(kt4 * 32 + ((lane >> 4) << 4));
            uint32_t off = (uint32_t)(a_r * 128) + (cb ^ ax);
            ldsm4(qh[mt][kt4], QB + off);
        }
    }

    float O[2][8][4];
#pragma unroll
    for (int mt = 0; mt < 2; mt++)
#pragma unroll
        for (int nt = 0; nt < 8; nt++)
#pragma unroll
            for (int j = 0; j < 4; j++) O[mt][nt][j] = 0.f;

    float snk = sinks[h];
    float mxA[2] = {snk, snk}, mxB[2] = {snk, snk};
    float lA[2] = {1.f, 1.f}, lB[2] = {1.f, 1.f};

    const int rbase = qt * 128 + w * 32 + (lane >> 2);
    const int wrow_max = qt * 128 + w * 32 + 31;       // this warp's largest q row
    const int b_rbase = ((lane >> 4) << 3) + (lane & 7);
    const uint32_t bsel = (uint32_t)(((lane >> 3) & 1) * 16);
    const int KT = 2 * qt + 2;

    for (int kt = 0; kt < KT; kt++) {
        if (kt + 1 < KT)
            stage_kv(KVB + ((kt + 1) & 1) * ATT_STAGE, kt + 1, kv, tid);
        asm volatile("cp.async.commit_group;" ::: "memory");
        asm volatile("cp.async.wait_group 1;" ::: "memory");
        __syncthreads();

        // fully-masked warp tile: every key > every row -> exact no-op
        if (kt * 64 > wrow_max) {
            __syncthreads();
            continue;
        }

        const uint32_t kb = KVB + (kt & 1) * ATT_STAGE;
        const uint32_t vb = kb + 8192;

        float sc[2][8][4];
#pragma unroll
        for (int mt = 0; mt < 2; mt++)
#pragma unroll
            for (int nt = 0; nt < 8; nt++)
#pragma unroll
                for (int j = 0; j < 4; j++) sc[mt][nt][j] = 0.f;

#pragma unroll
        for (int kt4 = 0; kt4 < 4; kt4++) {
#pragma unroll
            for (int kg = 0; kg < 4; kg++) {
                int b_r = kg * 16 + b_rbase;
                uint32_t off = (uint32_t)(b_r * 128) + (((uint32_t)(kt4 * 32) + bsel) ^ ((uint32_t)((b_r & 7) << 4)));
                uint32_t bh4[4];
                ldsm4(bh4, kb + off);
#pragma unroll
                for (int mt = 0; mt < 2; mt++) {
#pragma unroll
                    for (int n2 = 0; n2 < 2; n2++) {
                        mma_f16(sc[mt][2 * kg + n2], qh[mt][kt4], &bh4[n2 * 2]);
                    }
                }
            }
        }

        if (kt >= 2 * qt) {
#pragma unroll
            for (int mt = 0; mt < 2; mt++) {
                int row = rbase + mt * 16;
#pragma unroll
                for (int nt = 0; nt < 8; nt++) {
                    int key = kt * 64 + nt * 8 + 2 * (lane & 3);
                    if (key > row)         sc[mt][nt][0] = -1e30f;
                    if (key + 1 > row)     sc[mt][nt][1] = -1e30f;
                    if (key > row + 8)     sc[mt][nt][2] = -1e30f;
                    if (key + 1 > row + 8) sc[mt][nt][3] = -1e30f;
                }
            }
        }

#pragma unroll
        for (int mt = 0; mt < 2; mt++) {
            float r0 = -1e30f, r1 = -1e30f;
#pragma unroll
            for (int nt = 0; nt < 8; nt++) {
                r0 = fmaxf(r0, fmaxf(sc[mt][nt][0], sc[mt][nt][1]));
                r1 = fmaxf(r1, fmaxf(sc[mt][nt][2], sc[mt][nt][3]));
            }
            r0 = fmaxf(r0, __shfl_xor_sync(0xffffffffu, r0, 1));
            r0 = fmaxf(r0, __shfl_xor_sync(0xffffffffu, r0, 2));
            r1 = fmaxf(r1, __shfl_xor_sync(0xffffffffu, r1, 1));
            r1 = fmaxf(r1, __shfl_xor_sync(0xffffffffu, r1, 2));
            float mA2 = fmaxf(mxA[mt], r0), mB2 = fmaxf(mxB[mt], r1);
            float cA = __expf(mxA[mt] - mA2), cB = __expf(mxB[mt] - mB2);
            mxA[mt] = mA2; mxB[mt] = mB2;

            float sA = 0.f, sB = 0.f;
#pragma unroll
            for (int nt = 0; nt < 8; nt++) {
                sc[mt][nt][0] = __expf(sc[mt][nt][0] - mA2);
                sc[mt][nt][1] = __expf(sc[mt][nt][1] - mA2);
                sc[mt][nt][2] = __expf(sc[mt][nt][2] - mB2);
                sc[mt][nt][3] = __expf(sc[mt][nt][3] - mB2);
                sA += sc[mt][nt][0] + sc[mt][nt][1];
                sB += sc[mt][nt][2] + sc[mt][nt][3];
            }
            sA += __shfl_xor_sync(0xffffffffu, sA, 1);
            sA += __shfl_xor_sync(0xffffffffu, sA, 2);
            sB += __shfl_xor_sync(0xffffffffu, sB, 1);
            sB += __shfl_xor_sync(0xffffffffu, sB, 2);
            lA[mt] = lA[mt] * cA + sA;
            lB[mt] = lB[mt] * cB + sB;
#pragma unroll
            for (int nt = 0; nt < 8; nt++) {
                O[mt][nt][0] *= cA; O[mt][nt][1] *= cA;
                O[mt][nt][2] *= cB; O[mt][nt][3] *= cB;
            }
        }

#pragma unroll
        for (int sg = 0; sg < 4; sg++) {
            uint32_t ph[2][4];
#pragma unroll
            for (int mt = 0; mt < 2; mt++) {
                ph[mt][0] = pack_h2(sc[mt][2 * sg][0], sc[mt][2 * sg][1]);
                ph[mt][1] = pack_h2(sc[mt][2 * sg][2], sc[mt][2 * sg][3]);
                ph[mt][2] = pack_h2(sc[mt][2 * sg + 1][0], sc[mt][2 * sg + 1][1]);
                ph[mt][3] = pack_h2(sc[mt][2 * sg + 1][2], sc[mt][2 * sg + 1][3]);
            }
#pragma unroll
            for (int dg = 0; dg < 4; dg++) {
                int b_r = dg * 16 + b_rbase;
                uint32_t off = (uint32_t)(b_r * 128) + (((uint32_t)(sg * 32) + bsel) ^ ((uint32_t)((b_r & 7) << 4)));
                uint32_t vh4[4];
                ldsm4(vh4, vb + off);
#pragma unroll
                for (int mt = 0; mt < 2; mt++) {
#pragma unroll
                    for (int n2 = 0; n2 < 2; n2++) {
                        mma_f16(O[mt][2 * dg + n2], ph[mt], &vh4[n2 * 2]);
                    }
                }
            }
        }
        __syncthreads();
    }

#pragma unroll
    for (int mt = 0; mt < 2; mt++) {
        float iA = 1.f / lA[mt], iB = 1.f / lB[mt];
        int row = rbase + mt * 16;
        size_t r0o = (size_t)row * QDIM + h * 64;
        size_t r1o = r0o + (size_t)8 * QDIM;
#pragma unroll
        for (int nt = 0; nt < 8; nt++) {
            int c = nt * 8 + 2 * (lane & 3);
            *(uint32_t*)(g_o_h + r0o + c) = pack_h2(O[mt][nt][0] * iA, O[mt][nt][1] * iA);
            *(uint32_t*)(g_o_h + r1o + c) = pack_h2(O[mt][nt][2] * iB, O[mt][nt][3] * iB);
        }
    }
}

// ============================================================
// launch
// ============================================================
extern "C" void kernel_launch(void* const* d_in, const int* in_sizes, int n_in,
                              void* d_out, int out_size) {
    const float* x          = (const float*)d_in[0];
    const float* sinks      = (const float*)d_in[1];
    const float* norm_scale = (const float*)d_in[2];
    const float* qkv_w      = (const float*)d_in[3];
    const float* qkv_b      = (const float*)d_in[4];
    const float* out_w      = (const float*)d_in[5];
    const float* out_b      = (const float*)d_in[6];
    float* out = (float*)d_out;

    __half *th, *w1, *w2, *oh;
    cudaGetSymbolAddress((void**)&th, g_t_h);
    cudaGetSymbolAddress((void**)&w1, g_w1);
    cudaGetSymbolAddress((void**)&w2, g_w2);
    cudaGetSymbolAddress((void**)&oh, g_o_h);

    cudaFuncSetAttribute(gemm_mma<0>, cudaFuncAttributeMaxDynamicSharedMemorySize, SMEM_TOTAL_GEMM);
    cudaFuncSetAttribute(gemm_mma<1>, cudaFuncAttributeMaxDynamicSharedMemorySize, SMEM_TOTAL_GEMM);
    cudaFuncSetAttribute(attn_mma_kernel, cudaFuncAttributeMaxDynamicSharedMemorySize, ATT_SMEM_TOTAL);

    // rope tables FIRST (qkv epilogue consumes them)
    rope_tables_kernel<<<(S_TOK * 32 + 255) / 256, 256>>>();

    // both weight converts in one launch
    convert_both_kernel<<<NB_W1 + NB_W2, 256>>>((const float4*)qkv_w, (const float4*)out_w);

    rmsnorm_kernel<<<S_TOK, 256>>>(x, norm_scale);

    // qkv GEMM with fused bias+rope+scale epilogue -> g_q_h / g_k_h / g_vt_h
    gemm_mma<1><<<dim3(QKV_DIM / BN, S_TOK / BM), 128, SMEM_TOTAL_GEMM>>>(
        th, w1, qkv_b, nullptr, nullptr, S_TOK, QKV_DIM, HID);

    // tensorized attention (128-row q tiles, double-buffered KV, masked-tile skip)
    attn_mma_kernel<<<dim3(S_TOK / 128, NH), 128, ATT_SMEM_TOTAL>>>(sinks);

    // y = o @ out_w^T + out_b + x
    gemm_mma<0><<<dim3((HID + BN - 1) / BN, S_TOK / BM), 128, SMEM_TOTAL_GEMM>>>(
        oh, w2, out_b, x, out, S_TOK, HID, QDIM);
}

// round 15
// speedup vs baseline: 1.1890x; 1.0008x over previous
#include <cuda_runtime.h>
#include <cuda_fp16.h>
#include <cstdint>
#include <math.h>

// ---------------- problem constants ----------------
#define S_TOK   1536
#define HID     2880
#define NH      64
#define NKV     8
#define DH      64
#define QKV_DIM 5120
#define QDIM    4096
#define KOFF    4096
#define VOFF    4608
#define SM_SCALE 0.125f

// ---------------- scratch ----------------
__device__ __half g_t_h[S_TOK * HID];
__device__ __half g_w1[QKV_DIM * HID];
__device__ __half g_w2[HID * QDIM];
__device__ __half g_q_h[S_TOK * QDIM];
__device__ __half g_k_h[NKV * S_TOK * DH];
__device__ __half g_vt_h[NKV * DH * S_TOK];
__device__ __half g_o_h[S_TOK * QDIM];
__device__ float g_cos[S_TOK * 32];
__device__ float g_sin[S_TOK * 32];

// ---------------- helpers ----------------
__device__ __forceinline__ uint32_t smem_u32(const void* p) {
    uint32_t a;
    asm("{ .reg .u64 t; cvta.to.shared.u64 t, %1; cvt.u32.u64 %0, t; }" : "=r"(a) : "l"(p));
    return a;
}

__device__ __forceinline__ void ldsm4(uint32_t* r, uint32_t addr) {
    asm volatile("ldmatrix.sync.aligned.m8n8.x4.shared.b16 {%0,%1,%2,%3}, [%4];"
                 : "=r"(r[0]), "=r"(r[1]), "=r"(r[2]), "=r"(r[3]) : "r"(addr));
}

__device__ __forceinline__ void mma_f16(float* c, const uint32_t* a, const uint32_t* b) {
    asm volatile("mma.sync.aligned.m16n8k16.row.col.f32.f16.f16.f32 "
                 "{%0,%1,%2,%3}, {%4,%5,%6,%7}, {%8,%9}, {%0,%1,%2,%3};"
                 : "+f"(c[0]), "+f"(c[1]), "+f"(c[2]), "+f"(c[3])
                 : "r"(a[0]), "r"(a[1]), "r"(a[2]), "r"(a[3]), "r"(b[0]), "r"(b[1]));
}

__device__ __forceinline__ uint32_t pack_h2(float a, float b) {
    __half2 h = __floats2half2_rn(a, b);
    return *(uint32_t*)&h;
}

// ============================================================
// 1) RMSNorm -> fp16
// ============================================================
__global__ void rmsnorm_kernel(const float* __restrict__ x,
                               const float* __restrict__ scale) {
    int s = blockIdx.x;
    const float4* xr = (const float4*)(x + (size_t)s * HID);
    const float4* sc = (const float4*)scale;

    float ss = 0.f;
    for (int i = threadIdx.x; i < HID / 4; i += blockDim.x) {
        float4 v = xr[i];
        ss += v.x * v.x + v.y * v.y + v.z * v.z + v.w * v.w;
    }
    for (int o = 16; o > 0; o >>= 1) ss += __shfl_xor_sync(0xffffffff, ss, o);
    __shared__ float red[8];
    int wid = threadIdx.x >> 5, lid = threadIdx.x & 31;
    if (lid == 0) red[wid] = ss;
    __syncthreads();
    if (wid == 0) {
        float v = (lid < (blockDim.x >> 5)) ? red[lid] : 0.f;
        for (int o = 4; o > 0; o >>= 1) v += __shfl_xor_sync(0xffffffff, v, o);
        if (lid == 0) red[0] = v;
    }
    __syncthreads();
    float r = rsqrtf(red[0] / (float)HID + 1e-5f);

    uint2* th = (uint2*)(g_t_h + (size_t)s * HID);
    for (int i = threadIdx.x; i < HID / 4; i += blockDim.x) {
        float4 v = xr[i];
        float4 g = sc[i];
        uint2 hh;
        hh.x = pack_h2(v.x * r * g.x, v.y * r * g.y);
        hh.y = pack_h2(v.z * r * g.z, v.w * r * g.w);
        th[i] = hh;
    }
}

// ============================================================
// 2) fp32 -> fp16 convert: both weights in ONE launch
// ============================================================
#define NB_W1 14400
#define NB_W2 11520

__global__ void __launch_bounds__(256)
convert_both_kernel(const float4* __restrict__ w1src, const float4* __restrict__ w2src) {
    int b = blockIdx.x;
    if (b < NB_W1) {
        int i = b * 256 + threadIdx.x;
        float4 v = w1src[i];
        uint2 o;
        o.x = pack_h2(v.x, v.y);
        o.y = pack_h2(v.z, v.w);
        ((uint2*)g_w1)[i] = o;
    } else {
        int i = (b - NB_W1) * 256 + threadIdx.x;
        float4 v = w2src[i];
        uint2 o;
        o.x = pack_h2(v.x, v.y);
        o.y = pack_h2(v.z, v.w);
        ((uint2*)g_w2)[i] = o;
    }
}

// ============================================================
// 3) YaRN RoPE tables (fp64, matches reference) — runs FIRST
// ============================================================
__global__ void rope_tables_kernel() {
    int gid = blockIdx.x * blockDim.x + threadIdx.x;
    if (gid >= S_TOK * 32) return;
    int s = gid >> 5;
    int i = gid & 31;
    const double TWO_PI = 6.283185307179586;
    double freq = pow(150000.0, (double)(2 * i) / 64.0);
    double conc = 0.1 * log(32.0) + 1.0;
    double lo = 32.0 * log(4096.0 / (32.0 * TWO_PI)) / log(150000.0);
    double hi = 32.0 * log(4096.0 / (1.0 * TWO_PI)) / log(150000.0);
    double interp = 1.0 / (32.0 * freq);
    double extrap = 1.0 / freq;
    double ramp = ((double)i - lo) / (hi - lo);
    double mask = 1.0 - fmin(fmax(ramp, 0.0), 1.0);
    double invf = interp * (1.0 - mask) + extrap * mask;
    double f = (double)s * invf;
    g_cos[gid] = (float)(cos(f) * conc);
    g_sin[gid] = (float)(sin(f) * conc);
}

// ============================================================
// 4) mma.sync fp16 GEMM: CTA 128x128x64, 128 threads, 64x64 warp tile
//    fragment loads double-buffered at ks granularity
// ============================================================
#define BM 128
#define BN 128
#define BK 64
#define TILE_B 16384
#define STAGE_B (2 * TILE_B)
#define GEMM_STAGES 3
#define SMEM_TOTAL_GEMM (GEMM_STAGES * STAGE_B + 1024)

__device__ __forceinline__ void load_tile_128(uint32_t sbase, const __half* __restrict__ g,
                                              int row0, int nrows, int ldk, int k0, int tid) {
#pragma unroll
    for (int u = 0; u < 8; u++) {
        int unit = u * 128 + tid;
        int r = unit >> 3;
        int c16 = unit & 7;
        uint32_t off = (uint32_t)(r * 128 + ((c16 * 16) ^ ((r & 7) << 4)));
        int gr = row0 + r;
        int ok = (gr < nrows) ? 16 : 0;
        const __half* src = g + (size_t)((gr < nrows) ? gr : 0) * ldk + k0 + c16 * 8;
        asm volatile("cp.async.cg.shared.global [%0], [%1], 16, %2;"
                     :: "r"(sbase + off), "l"(src), "r"(ok) : "memory");
    }
}

__device__ __forceinline__ void load_stage(uint32_t st,
                                           const __half* A, const __half* B,
                                           int bm, int bn, int M, int N, int K, int k0, int tid) {
    load_tile_128(st,          A, bm, M, K, k0, tid);
    load_tile_128(st + TILE_B, B, bn, N, K, k0, tid);
}

__device__ __forceinline__ void load_frags(uint32_t st, int ks, int a_r, uint32_t a_cx,
                                           int b_r, uint32_t b_cx, int lane,
                                           uint32_t ah[4][4], uint32_t bh[4][4]) {
    const uint32_t acb = (uint32_t)(ks * 32 + ((lane >> 4) << 4));
#pragma unroll
    for (int mt = 0; mt < 4; mt++) {
        uint32_t off = (uint32_t)((a_r + mt * 16) * 128) + (acb ^ a_cx);
        ldsm4(ah[mt], st + off);
    }
    const uint32_t bcb = (uint32_t)(ks * 32 + ((lane >> 3) & 1) * 16);
#pragma unroll
    for (int p = 0; p < 4; p++) {
        uint32_t off = (uint32_t)((b_r + p * 16) * 128) + (bcb ^ b_cx);
        ldsm4(bh[p], st + TILE_B + off);
    }
}

template <int MODE>
__global__ void __launch_bounds__(128, 2)
gemm_mma(const __half* __restrict__ A, const __half* __restrict__ B,
         const float* __restrict__ bias, const float* __restrict__ resid,
         float* __restrict__ C, int M, int N, int K) {
    extern __shared__ char smem_raw[];
    uint32_t sb = (smem_u32(smem_raw) + 1023u) & ~1023u;

    const int tid = threadIdx.x;
    const int wid = tid >> 5;
    const int lane = tid & 31;
    const int wm = wid & 1;
    const int wn = wid >> 1;
    const int bm = blockIdx.y * BM;
    const int bn = blockIdx.x * BN;

    float acc[4][8][4];
#pragma unroll
    for (int i = 0; i < 4; i++)
#pragma unroll
        for (int j = 0; j < 8; j++)
#pragma unroll
            for (int k = 0; k < 4; k++) acc[i][j][k] = 0.f;

    const int a_r = wm * 64 + (lane & 15);
    const uint32_t a_cx = (uint32_t)((a_r & 7) << 4);
    const int b_r = wn * 64 + ((lane >> 4) << 3) + (lane & 7);
    const uint32_t b_cx = (uint32_t)((b_r & 7) << 4);

    const int NC = K / BK;

#pragma unroll
    for (int c = 0; c < 2; c++) {
        load_stage(sb + c * STAGE_B, A, B, bm, bn, M, N, K, c * BK, tid);
        asm volatile("cp.async.commit_group;" ::: "memory");
    }

    uint32_t ah[2][4][4], bh[2][4][4];

    for (int c = 0; c < NC; c++) {
        int pf = c + 2;
        if (pf < NC) {
            load_stage(sb + (pf % GEMM_STAGES) * STAGE_B, A, B, bm, bn, M, N, K, pf * BK, tid);
        }
        asm volatile("cp.async.commit_group;" ::: "memory");
        asm volatile("cp.async.wait_group 2;" ::: "memory");
        __syncthreads();

        const uint32_t st = sb + (c % GEMM_STAGES) * STAGE_B;

        // ks-pipelined fragment loads
        load_frags(st, 0, a_r, a_cx, b_r, b_cx, lane, ah[0], bh[0]);
#pragma unroll
        for (int ks = 0; ks < 4; ks++) {
            const int cur = ks & 1;
            if (ks < 3)
                load_frags(st, ks + 1, a_r, a_cx, b_r, b_cx, lane, ah[cur ^ 1], bh[cur ^ 1]);
#pragma unroll
            for (int mt = 0; mt < 4; mt++) {
#pragma unroll
                for (int nt = 0; nt < 8; nt++) {
                    mma_f16(acc[mt][nt], ah[cur][mt], &bh[cur][nt >> 1][(nt & 1) * 2]);
                }
            }
        }
        __syncthreads();
    }

    const int row0 = bm + wm * 64;
    const int col0 = bn + wn * 64;

    if (MODE == 0) {
#pragma unroll
        for (int mt = 0; mt < 4; mt++) {
#pragma unroll
            for (int nt = 0; nt < 8; nt++) {
                int r = row0 + mt * 16 + (lane >> 2);
                int c0 = col0 + nt * 8 + (lane & 3) * 2;
                if (c0 < N) {
                    float bx = bias[c0], by = bias[c0 + 1];
                    float2 v0, v1;
                    v0.x = acc[mt][nt][0] + bx; v0.y = acc[mt][nt][1] + by;
                    v1.x = acc[mt][nt][2] + bx; v1.y = acc[mt][nt][3] + by;
                    const float2 x0 = *(const float2*)(resid + (size_t)r * N + c0);
                    const float2 x1 = *(const float2*)(resid + (size_t)(r + 8) * N + c0);
                    v0.x += x0.x; v0.y += x0.y;
                    v1.x += x1.x; v1.y += x1.y;
                    *(float2*)(C + (size_t)r * N + c0) = v0;
                    *(float2*)(C + (size_t)(r + 8) * N + c0) = v1;
                }
            }
        }
    } else {
        const int head_blk = col0 >> 6;
        if (head_blk < 64) {
#pragma unroll
            for (int mt = 0; mt < 4; mt++) {
                int r = row0 + mt * 16 + (lane >> 2);
#pragma unroll
                for (int nt = 0; nt < 4; nt++) {
                    int d = nt * 8 + (lane & 3) * 2;
                    int cA = col0 + d, cB = cA + 32;
                    float b1x = bias[cA], b1y = bias[cA + 1];
                    float b2x = bias[cB], b2y = bias[cB + 1];
                    float2 c0v = *(const float2*)(g_cos + r * 32 + d);
                    float2 s0v = *(const float2*)(g_sin + r * 32 + d);
                    float2 c1v = *(const float2*)(g_cos + (r + 8) * 32 + d);
                    float2 s1v = *(const float2*)(g_sin + (r + 8) * 32 + d);
                    float x1a = acc[mt][nt][0] + b1x, x1b = acc[mt][nt][1] + b1y;
                    float x2a = acc[mt][nt + 4][0] + b2x, x2b = acc[mt][nt + 4][1] + b2y;
                    size_t o = (size_t)r * QDIM + head_blk * 64 + d;
                    *(uint32_t*)(g_q_h + o) =
                        pack_h2((x1a * c0v.x - x2a * s0v.x) * SM_SCALE,
                                (x1b * c0v.y - x2b * s0v.y) * SM_SCALE);
                    *(uint32_t*)(g_q_h + o + 32) =
                        pack_h2((x2a * c0v.x + x1a * s0v.x) * SM_SCALE,
                                (x2b * c0v.y + x1b * s0v.y) * SM_SCALE);
                    float y1a = acc[mt][nt][2] + b1x, y1b = acc[mt][nt][3] + b1y;
                    float y2a = acc[mt][nt + 4][2] + b2x, y2b = acc[mt][nt + 4][3] + b2y;
                    size_t o8 = o + (size_t)8 * QDIM;
                    *(uint32_t*)(g_q_h + o8) =
                        pack_h2((y1a * c1v.x - y2a * s1v.x) * SM_SCALE,
                                (y1b * c1v.y - y2b * s1v.y) * SM_SCALE);
                    *(uint32_t*)(g_q_h + o8 + 32) =
                        pack_h2((y2a * c1v.x + y1a * s1v.x) * SM_SCALE,
                                (y2b * c1v.y + y1b * s1v.y) * SM_SCALE);
                }
            }
        } else if (head_blk < 72) {
            const int kvh = head_blk - 64;
#pragma unroll
            for (int mt = 0; mt < 4; mt++) {
                int r = row0 + mt * 16 + (lane >> 2);
#pragma unroll
                for (int nt = 0; nt < 4; nt++) {
                    int d = nt * 8 + (lane & 3) * 2;
                    int cA = col0 + d, cB = cA + 32;
                    float b1x = bias[cA], b1y = bias[cA + 1];
                    float b2x = bias[cB], b2y = bias[cB + 1];
                    float2 c0v = *(const float2*)(g_cos + r * 32 + d);
                    float2 s0v = *(const float2*)(g_sin + r * 32 + d);
                    float2 c1v = *(const float2*)(g_cos + (r + 8) * 32 + d);
                    float2 s1v = *(const float2*)(g_sin + (r + 8) * 32 + d);
                    float x1a = acc[mt][nt][0] + b1x, x1b = acc[mt][nt][1] + b1y;
                    float x2a = acc[mt][nt + 4][0] + b2x, x2b = acc[mt][nt + 4][1] + b2y;
                    size_t o = (size_t)kvh * S_TOK * DH + (size_t)r * DH + d;
                    *(uint32_t*)(g_k_h + o) =
                        pack_h2(x1a * c0v.x - x2a * s0v.x, x1b * c0v.y - x2b * s0v.y);
                    *(uint32_t*)(g_k_h + o + 32) =
                        pack_h2(x2a * c0v.x + x1a * s0v.x, x2b * c0v.y + x1b * s0v.y);
                    float y1a = acc[mt][nt][2] + b1x, y1b = acc[mt][nt][3] + b1y;
                    float y2a = acc[mt][nt + 4][2] + b2x, y2b = acc[mt][nt + 4][3] + b2y;
                    size_t o8 = o + (size_t)8 * DH;
                    *(uint32_t*)(g_k_h + o8) =
                        pack_h2(y1a * c1v.x - y2a * s1v.x, y1b * c1v.y - y2b * s1v.y);
                    *(uint32_t*)(g_k_h + o8 + 32) =
                        pack_h2(y2a * c1v.x + y1a * s1v.x, y2b * c1v.y + y1b * s1v.y);
                }
            }
        } else {
            const int kvh = head_blk - 72;
            __half* vt = g_vt_h + (size_t)kvh * DH * S_TOK;
#pragma unroll
            for (int mt = 0; mt < 4; mt++) {
                int r = row0 + mt * 16 + (lane >> 2);
#pragma unroll
                for (int nt = 0; nt < 8; nt++) {
                    int d = nt * 8 + (lane & 3) * 2;
                    float bx = bias[col0 + d], by = bias[col0 + d + 1];
                    vt[(size_t)d * S_TOK + r]           = __float2half_rn(acc[mt][nt][0] + bx);
                    vt[(size_t)(d + 1) * S_TOK + r]     = __float2half_rn(acc[mt][nt][1] + by);
                    vt[(size_t)d * S_TOK + r + 8]       = __float2half_rn(acc[mt][nt][2] + bx);
                    vt[(size_t)(d + 1) * S_TOK + r + 8] = __float2half_rn(acc[mt][nt][3] + by);
                }
            }
        }
    }
}

// ============================================================
// 5) tensorized flash attention with sinks
//    block: 128 q rows x 1 head, 4 warps; masked-tile skip
// ============================================================
#define ATT_STAGE 16384
#define ATT_SMEM_TOTAL (1024 + 16384 + 2 * ATT_STAGE)

__device__ __forceinline__ void stage128q(uint32_t sbase, const __half* __restrict__ g,
                                          int row_stride, int tid) {
#pragma unroll
    for (int u = 0; u < 8; u++) {
        int unit = u * 128 + tid;
        int r = unit >> 3, c16 = unit & 7;
        uint32_t off = (uint32_t)(r * 128 + ((c16 * 16) ^ ((r & 7) << 4)));
        const __half* src = g + (size_t)r * row_stride + c16 * 8;
        asm volatile("cp.async.cg.shared.global [%0], [%1], 16;"
                     :: "r"(sbase + off), "l"(src) : "memory");
    }
}

__device__ __forceinline__ void stage64(uint32_t sbase, const __half* __restrict__ g,
                                        int row_stride, int tid) {
#pragma unroll
    for (int u = 0; u < 4; u++) {
        int unit = u * 128 + tid;
        int r = unit >> 3, c16 = unit & 7;
        uint32_t off = (uint32_t)(r * 128 + ((c16 * 16) ^ ((r & 7) << 4)));
        const __half* src = g + (size_t)r * row_stride + c16 * 8;
        asm volatile("cp.async.cg.shared.global [%0], [%1], 16;"
                     :: "r"(sbase + off), "l"(src) : "memory");
    }
}

__device__ __forceinline__ void stage_kv(uint32_t base, int kt, int kv, int tid) {
    const __half* kh = g_k_h + (size_t)kv * S_TOK * DH + (size_t)kt * 64 * DH;
    const __half* vh = g_vt_h + (size_t)kv * DH * S_TOK + kt * 64;
    stage64(base,        kh, DH, tid);
    stage64(base + 8192, vh, S_TOK, tid);
}

__global__ void __launch_bounds__(128)
attn_mma_kernel(const float* __restrict__ sinks) {
    extern __shared__ char sraw[];
    uint32_t sb = (smem_u32(sraw) + 1023u) & ~1023u;
    const uint32_t QB = sb, KVB = sb + 16384;

    const int qt = (int)gridDim.x - 1 - (int)blockIdx.x;
    const int h = blockIdx.y, kv = h & 7;
    const int tid = threadIdx.x, w = tid >> 5, lane = tid & 31;

    stage128q(QB, g_q_h + (size_t)(qt * 128) * QDIM + h * 64, QDIM, tid);
    stage_kv(KVB, 0, kv, tid);
    asm volatile("cp.async.commit_group;" ::: "memory");
    asm volatile("cp.async.wait_group 0;" ::: "memory");
    __syncthreads();

    uint32_t qh[2][4][4];
#pragma unroll
    for (int mt = 0; mt < 2; mt++) {
        int a_r = w * 32 + mt * 16 + (lane & 15);
        uint32_t ax = (uint32_t)((a_r & 7) << 4);
#pragma unroll
        for (int kt4 = 0; kt4 < 4; kt4++) {
            uint32_t cb = (uint32_t)(kt4 * 32 + ((lane >> 4) << 4));
            uint32_t off = (uint32_t)(a_r * 128) + (cb ^ ax);
            ldsm4(qh[mt][kt4], QB + off);
        }
    }

    float O[2][8][4];
#pragma unroll
    for (int mt = 0; mt < 2; mt++)
#pragma unroll
        for (int nt = 0; nt < 8; nt++)
#pragma unroll
            for (int j = 0; j < 4; j++) O[mt][nt][j] = 0.f;

    float snk = sinks[h];
    float mxA[2] = {snk, snk}, mxB[2] = {snk, snk};
    float lA[2] = {1.f, 1.f}, lB[2] = {1.f, 1.f};

    const int rbase = qt * 128 + w * 32 + (lane >> 2);
    const int wrow_max = qt * 128 + w * 32 + 31;
    const int b_rbase = ((lane >> 4) << 3) + (lane & 7);
    const uint32_t bsel = (uint32_t)(((lane >> 3) & 1) * 16);
    const int KT = 2 * qt + 2;

    for (int kt = 0; kt < KT; kt++) {
        if (kt + 1 < KT)
            stage_kv(KVB + ((kt + 1) & 1) * ATT_STAGE, kt + 1, kv, tid);
        asm volatile("cp.async.commit_group;" ::: "memory");
        asm volatile("cp.async.wait_group 1;" ::: "memory");
        __syncthreads();

        if (kt * 64 > wrow_max) {
            __syncthreads();
            continue;
        }

        const uint32_t kb = KVB + (kt & 1) * ATT_STAGE;
        const uint32_t vb = kb + 8192;

        float sc[2][8][4];
#pragma unroll
        for (int mt = 0; mt < 2; mt++)
#pragma unroll
            for (int nt = 0; nt < 8; nt++)
#pragma unroll
                for (int j = 0; j < 4; j++) sc[mt][nt][j] = 0.f;

#pragma unroll
        for (int kt4 = 0; kt4 < 4; kt4++) {
#pragma unroll
            for (int kg = 0; kg < 4; kg++) {
                int b_r = kg * 16 + b_rbase;
                uint32_t off = (uint32_t)(b_r * 128) + (((uint32_t)(kt4 * 32) + bsel) ^ ((uint32_t)((b_r & 7) << 4)));
                uint32_t bh4[4];
                ldsm4(bh4, kb + off);
#pragma unroll
                for (int mt = 0; mt < 2; mt++) {
#pragma unroll
                    for (int n2 = 0; n2 < 2; n2++) {
                        mma_f16(sc[mt][2 * kg + n2], qh[mt][kt4], &bh4[n2 * 2]);
                    }
                }
            }
        }

        if (kt >= 2 * qt) {
#pragma unroll
            for (int mt = 0; mt < 2; mt++) {
                int row = rbase + mt * 16;
#pragma unroll
                for (int nt = 0; nt < 8; nt++) {
                    int key = kt * 64 + nt * 8 + 2 * (lane & 3);
                    if (key > row)         sc[mt][nt][0] = -1e30f;
                    if (key + 1 > row)     sc[mt][nt][1] = -1e30f;
                    if (key > row + 8)     sc[mt][nt][2] = -1e30f;
                    if (key + 1 > row + 8) sc[mt][nt][3] = -1e30f;
                }
            }
        }

#pragma unroll
        for (int mt = 0; mt < 2; mt++) {
            float r0 = -1e30f, r1 = -1e30f;
#pragma unroll
            for (int nt = 0; nt < 8; nt++) {
                r0 = fmaxf(r0, fmaxf(sc[mt][nt][0], sc[mt][nt][1]));
                r1 = fmaxf(r1, fmaxf(sc[mt][nt][2], sc[mt][nt][3]));
            }
            r0 = fmaxf(r0, __shfl_xor_sync(0xffffffffu, r0, 1));
            r0 = fmaxf(r0, __shfl_xor_sync(0xffffffffu, r0, 2));
            r1 = fmaxf(r1, __shfl_xor_sync(0xffffffffu, r1, 1));
            r1 = fmaxf(r1, __shfl_xor_sync(0xffffffffu, r1, 2));
            float mA2 = fmaxf(mxA[mt], r0), mB2 = fmaxf(mxB[mt], r1);
            float cA = __expf(mxA[mt] - mA2), cB = __expf(mxB[mt] - mB2);
            mxA[mt] = mA2; mxB[mt] = mB2;

            float sA = 0.f, sB = 0.f;
#pragma unroll
            for (int nt = 0; nt < 8; nt++) {
                sc[mt][nt][0] = __expf(sc[mt][nt][0] - mA2);
                sc[mt][nt][1] = __expf(sc[mt][nt][1] - mA2);
                sc[mt][nt][2] = __expf(sc[mt][nt][2] - mB2);
                sc[mt][nt][3] = __expf(sc[mt][nt][3] - mB2);
                sA += sc[mt][nt][0] + sc[mt][nt][1];
                sB += sc[mt][nt][2] + sc[mt][nt][3];
            }
            sA += __shfl_xor_sync(0xffffffffu, sA, 1);
            sA += __shfl_xor_sync(0xffffffffu, sA, 2);
            sB += __shfl_xor_sync(0xffffffffu, sB, 1);
            sB += __shfl_xor_sync(0xffffffffu, sB, 2);
            lA[mt] = lA[mt] * cA + sA;
            lB[mt] = lB[mt] * cB + sB;
#pragma unroll
            for (int nt = 0; nt < 8; nt++) {
                O[mt][nt][0] *= cA; O[mt][nt][1] *= cA;
                O[mt][nt][2] *= cB; O[mt][nt][3] *= cB;
            }
        }

#pragma unroll
        for (int sg = 0; sg < 4; sg++) {
            uint32_t ph[2][4];
#pragma unroll
            for (int mt = 0; mt < 2; mt++) {
                ph[mt][0] = pack_h2(sc[mt][2 * sg][0], sc[mt][2 * sg][1]);
                ph[mt][1] = pack_h2(sc[mt][2 * sg][2], sc[mt][2 * sg][3]);
                ph[mt][2] = pack_h2(sc[mt][2 * sg + 1][0], sc[mt][2 * sg + 1][1]);
                ph[mt][3] = pack_h2(sc[mt][2 * sg + 1][2], sc[mt][2 * sg + 1][3]);
            }
#pragma unroll
            for (int dg = 0; dg < 4; dg++) {
                int b_r = dg * 16 + b_rbase;
                uint32_t off = (uint32_t)(b_r * 128) + (((uint32_t)(sg * 32) + bsel) ^ ((uint32_t)((b_r & 7) << 4)));
                uint32_t vh4[4];
                ldsm4(vh4, vb + off);
#pragma unroll
                for (int mt = 0; mt < 2; mt++) {
#pragma unroll
                    for (int n2 = 0; n2 < 2; n2++) {
                        mma_f16(O[mt][2 * dg + n2], ph[mt], &vh4[n2 * 2]);
                    }
                }
            }
        }
        __syncthreads();
    }

#pragma unroll
    for (int mt = 0; mt < 2; mt++) {
        float iA = 1.f / lA[mt], iB = 1.f / lB[mt];
        int row = rbase + mt * 16;
        size_t r0o = (size_t)row * QDIM + h * 64;
        size_t r1o = r0o + (size_t)8 * QDIM;
#pragma unroll
        for (int nt = 0; nt < 8; nt++) {
            int c = nt * 8 + 2 * (lane & 3);
            *(uint32_t*)(g_o_h + r0o + c) = pack_h2(O[mt][nt][0] * iA, O[mt][nt][1] * iA);
            *(uint32_t*)(g_o_h + r1o + c) = pack_h2(O[mt][nt][2] * iB, O[mt][nt][3] * iB);
        }
    }
}

// ============================================================
// launch
// ============================================================
extern "C" void kernel_launch(void* const* d_in, const int* in_sizes, int n_in,
                              void* d_out, int out_size) {
    const float* x          = (const float*)d_in[0];
    const float* sinks      = (const float*)d_in[1];
    const float* norm_scale = (const float*)d_in[2];
    const float* qkv_w      = (const float*)d_in[3];
    const float* qkv_b      = (const float*)d_in[4];
    const float* out_w      = (const float*)d_in[5];
    const float* out_b      = (const float*)d_in[6];
    float* out = (float*)d_out;

    __half *th, *w1, *w2, *oh;
    cudaGetSymbolAddress((void**)&th, g_t_h);
    cudaGetSymbolAddress((void**)&w1, g_w1);
    cudaGetSymbolAddress((void**)&w2, g_w2);
    cudaGetSymbolAddress((void**)&oh, g_o_h);

    cudaFuncSetAttribute(gemm_mma<0>, cudaFuncAttributeMaxDynamicSharedMemorySize, SMEM_TOTAL_GEMM);
    cudaFuncSetAttribute(gemm_mma<1>, cudaFuncAttributeMaxDynamicSharedMemorySize, SMEM_TOTAL_GEMM);
    cudaFuncSetAttribute(attn_mma_kernel, cudaFuncAttributeMaxDynamicSharedMemorySize, ATT_SMEM_TOTAL);

    rope_tables_kernel<<<(S_TOK * 32 + 255) / 256, 256>>>();
    convert_both_kernel<<<NB_W1 + NB_W2, 256>>>((const float4*)qkv_w, (const float4*)out_w);
    rmsnorm_kernel<<<S_TOK, 256>>>(x, norm_scale);

    gemm_mma<1><<<dim3(QKV_DIM / BN, S_TOK / BM), 128, SMEM_TOTAL_GEMM>>>(
        th, w1, qkv_b, nullptr, nullptr, S_TOK, QKV_DIM, HID);

    attn_mma_kernel<<<dim3(S_TOK / 128, NH), 128, ATT_SMEM_TOTAL>>>(sinks);

    gemm_mma<0><<<dim3((HID + BN - 1) / BN, S_TOK / BM), 128, SMEM_TOTAL_GEMM>>>(
        oh, w2, out_b, x, out, S_TOK, HID, QDIM);
}